// round 17
// baseline (speedup 1.0000x reference)
#include <cuda_runtime.h>
#include <cuda_bf16.h>
#include <cuda_fp16.h>
#include <cstdint>
#include <math.h>

#define N 8192
#define EDIM 128
#define WFEAT 128
#define SLOPE 0.01f
#define NEGINF (-3.0e38f)
#define L2E 1.4426950408889634f

// ---------------- device scratch ----------------
__device__ __half g_h16[(size_t)N * WFEAT];      // h in fp16 (B operand)
__device__ float g_fsrc[N];
__device__ float g_fdst[N];
__device__ float g_rowC[N];
__device__ uint32_t g_mask[(size_t)N * 256];     // packed (adj+self)>0, 8MB
__device__ float g_pmax[256 * WFEAT];            // per-CTA column maxima

// ---------------- helpers ----------------
__device__ __forceinline__ uint32_t smem_u32(const void* p) {
    uint32_t a;
    asm("{ .reg .u64 t; cvta.to.shared.u64 t, %1; cvt.u32.u64 %0, t; }" : "=r"(a) : "l"(p));
    return a;
}
__device__ __forceinline__ void cp16(uint32_t dst, const void* src) {
    asm volatile("cp.async.cg.shared.global [%0], [%1], 16;" :: "r"(dst), "l"(src));
}
__device__ __forceinline__ void cp_commit() {
    asm volatile("cp.async.commit_group;");
}
__device__ __forceinline__ void cp_wait0() {
    asm volatile("cp.async.wait_group 0;");
}
__device__ __forceinline__ void ldsm_x4(uint32_t* r, uint32_t addr) {
    asm volatile("ldmatrix.sync.aligned.m8n8.x4.shared.b16 {%0,%1,%2,%3}, [%4];"
                 : "=r"(r[0]), "=r"(r[1]), "=r"(r[2]), "=r"(r[3]) : "r"(addr));
}
__device__ __forceinline__ void ldsm_x4_t(uint32_t* r, uint32_t addr) {
    asm volatile("ldmatrix.sync.aligned.m8n8.x4.trans.shared.b16 {%0,%1,%2,%3}, [%4];"
                 : "=r"(r[0]), "=r"(r[1]), "=r"(r[2]), "=r"(r[3]) : "r"(addr));
}
__device__ __forceinline__ void mma_f16(float* d, const uint32_t* a, const uint32_t* b) {
    asm volatile(
        "mma.sync.aligned.m16n8k16.row.col.f32.f16.f16.f32 "
        "{%0,%1,%2,%3}, {%4,%5,%6,%7}, {%8,%9}, {%0,%1,%2,%3};"
        : "+f"(d[0]), "+f"(d[1]), "+f"(d[2]), "+f"(d[3])
        : "r"(a[0]), "r"(a[1]), "r"(a[2]), "r"(a[3]), "r"(b[0]), "r"(b[1]));
}

// ---------------- K1: h = emb[inSen] @ W (fp16 h + f_src/f_dst) ----------------
__global__ __launch_bounds__(128) void k1_proj(const int* __restrict__ inSen,
                                               const float* __restrict__ emb,
                                               const float* __restrict__ W,
                                               const float* __restrict__ a_src,
                                               const float* __restrict__ a_dst) {
    __shared__ float Ws[64][128];
    __shared__ float wv[16][64];
    __shared__ int   sIdx[16];
    __shared__ float sa[128], sd[128];

    const int tid = threadIdx.x;
    const int i0  = blockIdx.x * 16;

    if (tid < 16) sIdx[tid] = inSen[i0 + tid];
    sa[tid] = a_src[tid];
    sd[tid] = a_dst[tid];
    __syncthreads();

    float acc[16];
#pragma unroll
    for (int r = 0; r < 16; r++) acc[r] = 0.f;

    const int r  = tid >> 3;
    const int p0 = (tid & 7) * 8;

    for (int kc = 0; kc < EDIM; kc += 64) {
#pragma unroll 8
        for (int dd = 0; dd < 64; dd++)
            Ws[dd][tid] = W[(size_t)(kc + dd) * WFEAT + tid];
        {
            const float* er = emb + (size_t)sIdx[r] * EDIM + kc;
#pragma unroll
            for (int p = 0; p < 8; p++) wv[r][p0 + p] = er[p0 + p];
        }
        __syncthreads();
#pragma unroll 16
        for (int dd = 0; dd < 64; dd++) {
            const float w = Ws[dd][tid];
#pragma unroll
            for (int rr = 0; rr < 16; rr++) acc[rr] += wv[rr][dd] * w;
        }
        __syncthreads();
    }
#pragma unroll
    for (int rr = 0; rr < 16; rr++) {
        const float v = acc[rr];
        g_h16[(size_t)(i0 + rr) * WFEAT + tid] = __float2half(v);
        Ws[rr][tid] = v;
    }
    __syncthreads();

    {
        const int rr  = tid >> 3;
        const int seg = (tid & 7) * 16;
        float ps = 0.f, pd = 0.f;
#pragma unroll
        for (int c2 = 0; c2 < 16; c2++) {
            const float hv = Ws[rr][seg + c2];
            ps += hv * sa[seg + c2];
            pd += hv * sd[seg + c2];
        }
#pragma unroll
        for (int off = 1; off < 8; off <<= 1) {
            ps += __shfl_xor_sync(0xffffffffu, ps, off);
            pd += __shfl_xor_sync(0xffffffffu, pd, off);
        }
        if ((tid & 7) == 0) {
            g_fsrc[i0 + rr] = ps;
            g_fdst[i0 + rr] = pd;
        }
    }
}

// ---------------- K2: row stats + packed mask ----------------
__global__ __launch_bounds__(256) void k2_stats(const int* __restrict__ adj,
                                                const int* __restrict__ selfLinkP) {
    const int i   = blockIdx.x;
    const int tid = threadIdx.x;
    const int lane = tid & 31;
    const int selfLink = *selfLinkP;
    const float si = g_fsrc[i];

    const int4* arow = (const int4*)(adj + (size_t)i * N);
    int4 aa[8];
    float4 ff[8];
#pragma unroll
    for (int k = 0; k < 8; k++) aa[k] = __ldg(arow + tid + (k << 8));
#pragma unroll
    for (int k = 0; k < 8; k++) ff[k] = __ldg((const float4*)&g_fdst[(tid + (k << 8)) << 2]);

    float tm = NEGINF;
#pragma unroll
    for (int k = 0; k < 8; k++) {
        const int idx4 = tid + (k << 8);
        const int j0 = idx4 << 2;
        const int m0 = aa[k].x + ((j0 + 0) == i ? selfLink : 0);
        const int m1 = aa[k].y + ((j0 + 1) == i ? selfLink : 0);
        const int m2 = aa[k].z + ((j0 + 2) == i ? selfLink : 0);
        const int m3 = aa[k].w + ((j0 + 3) == i ? selfLink : 0);

        float x0 = si + ff[k].x, x1 = si + ff[k].y, x2 = si + ff[k].z, x3 = si + ff[k].w;
        x0 = fmaxf(x0, SLOPE * x0);
        x1 = fmaxf(x1, SLOPE * x1);
        x2 = fmaxf(x2, SLOPE * x2);
        x3 = fmaxf(x3, SLOPE * x3);
        const float val0 = (m0 > 0) ? x0 : -1e9f;
        const float val1 = (m1 > 0) ? x1 : -1e9f;
        const float val2 = (m2 > 0) ? x2 : -1e9f;
        const float val3 = (m3 > 0) ? x3 : -1e9f;
        tm = fmaxf(tm, fmaxf(fmaxf(val0, val1), fmaxf(val2, val3)));

        uint32_t wp = ((uint32_t)(m0 > 0) | ((uint32_t)(m1 > 0) << 1) |
                       ((uint32_t)(m2 > 0) << 2) | ((uint32_t)(m3 > 0) << 3))
                      << ((lane & 7) * 4);
        wp |= __shfl_xor_sync(0xffffffffu, wp, 1);
        wp |= __shfl_xor_sync(0xffffffffu, wp, 2);
        wp |= __shfl_xor_sync(0xffffffffu, wp, 4);
        if ((lane & 7) == 0)
            g_mask[(size_t)i * 256 + (idx4 >> 3)] = wp;
    }
    __shared__ float smax[8];
#pragma unroll
    for (int off = 16; off > 0; off >>= 1) tm = fmaxf(tm, __shfl_xor_sync(0xffffffffu, tm, off));
    if ((tid & 31) == 0) smax[tid >> 5] = tm;
    __syncthreads();
    if (tid < 32) {
        float z = (tid < 8) ? smax[tid] : NEGINF;
#pragma unroll
        for (int off = 4; off > 0; off >>= 1) z = fmaxf(z, __shfl_xor_sync(0xffffffffu, z, off));
        if (tid == 0) smax[0] = z;
    }
    __syncthreads();
    const float M = smax[0];

    float ts = 0.f;
#pragma unroll
    for (int k = 0; k < 8; k++) {
        const int j0 = (tid + (k << 8)) << 2;
        const int m0 = aa[k].x + ((j0 + 0) == i ? selfLink : 0);
        const int m1 = aa[k].y + ((j0 + 1) == i ? selfLink : 0);
        const int m2 = aa[k].z + ((j0 + 2) == i ? selfLink : 0);
        const int m3 = aa[k].w + ((j0 + 3) == i ? selfLink : 0);
        float x0 = si + ff[k].x, x1 = si + ff[k].y, x2 = si + ff[k].z, x3 = si + ff[k].w;
        x0 = fmaxf(x0, SLOPE * x0);
        x1 = fmaxf(x1, SLOPE * x1);
        x2 = fmaxf(x2, SLOPE * x2);
        x3 = fmaxf(x3, SLOPE * x3);
        ts += __expf(((m0 > 0) ? x0 : -1e9f) - M);
        ts += __expf(((m1 > 0) ? x1 : -1e9f) - M);
        ts += __expf(((m2 > 0) ? x2 : -1e9f) - M);
        ts += __expf(((m3 > 0) ? x3 : -1e9f) - M);
    }
    __shared__ float ssum[8];
#pragma unroll
    for (int off = 16; off > 0; off >>= 1) ts += __shfl_xor_sync(0xffffffffu, ts, off);
    if ((tid & 31) == 0) ssum[tid >> 5] = ts;
    __syncthreads();
    if (tid == 0) {
        float S = 0.f;
#pragma unroll
        for (int w = 0; w < 8; w++) S += ssum[w];
        g_rowC[i] = fmaf(-M, L2E, -__log2f(S));
    }
}

// ---------------- K3: fp16 1-term, 128-K iterations ----------------
// smem (bytes): B ring 2 stages [0, 2*34816); A double [69632, +2*8704)
#define B_BUF 34816
#define SB_STRIDE 136
#define OFF_A 69632
#define A_BUF 8704
#define SA_STRIDE 136
#define K3_SMEM 87040
#define NIT (N / 128)

// stage-A for iteration it (128 j-cols) -> A fp16 buffer (+att global write)
__device__ __forceinline__ void stage_a(char* smem, uint32_t aBufOff, int it,
                                        float fs, float Cr,
                                        float* att_row, uint4 mw,
                                        const float4* d4, int arow, int baseCol) {
    const int jbase = it * 128;
    uint32_t wsel;
    {
        const int wi = baseCol >> 5;
        wsel = (wi == 0) ? mw.x : (wi == 1) ? mw.y : (wi == 2) ? mw.z : mw.w;
    }
#pragma unroll
    for (int g = 0; g < 4; g++) {
        const int jcol = baseCol + g * 4;
        const int jg = jbase + jcol;
        const int sh = jcol & 31;
        const float4 d = d4[g];

        float v0 = fs + d.x, v1 = fs + d.y, v2 = fs + d.z, v3 = fs + d.w;
        v0 = fmaxf(v0, SLOPE * v0);
        v1 = fmaxf(v1, SLOPE * v1);
        v2 = fmaxf(v2, SLOPE * v2);
        v3 = fmaxf(v3, SLOPE * v3);
        float r0 = (wsel & (1u << (sh + 0))) ? fmaf(v0, L2E, Cr) : -1e30f;
        float r1 = (wsel & (1u << (sh + 1))) ? fmaf(v1, L2E, Cr) : -1e30f;
        float r2 = (wsel & (1u << (sh + 2))) ? fmaf(v2, L2E, Cr) : -1e30f;
        float r3 = (wsel & (1u << (sh + 3))) ? fmaf(v3, L2E, Cr) : -1e30f;
        float a0, a1, a2, a3;
        asm("ex2.approx.f32 %0, %1;" : "=f"(a0) : "f"(r0));
        asm("ex2.approx.f32 %0, %1;" : "=f"(a1) : "f"(r1));
        asm("ex2.approx.f32 %0, %1;" : "=f"(a2) : "f"(r2));
        asm("ex2.approx.f32 %0, %1;" : "=f"(a3) : "f"(r3));

        __stcs((float4*)(att_row + jg), make_float4(a0, a1, a2, a3));

        __half2 p01 = __floats2half2_rn(a0, a1);
        __half2 p23 = __floats2half2_rn(a2, a3);
        const uint32_t ao = (arow * SA_STRIDE + jcol) * 2;
        *(uint2*)(smem + aBufOff + ao) =
            make_uint2(*(uint32_t*)&p01, *(uint32_t*)&p23);
    }
}

__global__ __launch_bounds__(256, 2) void k3_hmma(float* __restrict__ att_out,
                                                  float* __restrict__ sen_out) {
    extern __shared__ char smem[];
    const uint32_t sb = smem_u32(smem);

    const int tid = threadIdx.x;
    const int wid = tid >> 5;
    const int lane = tid & 31;
    const int i0 = blockIdx.x * 32;

    // stage-A mapping: 8 threads per row, 16 cols each
    const int arow = tid >> 3;
    const int baseCol = (tid & 7) * 16;
    const int gi = i0 + arow;
    const float fs = g_fsrc[gi];
    const float Cr = g_rowC[gi];
    float* att_row = att_out + (size_t)gi * N;
    const uint4* mrow4 = (const uint4*)(g_mask + (size_t)gi * 256);

    // B cp.async mapping: 128 rows x 17 seg16 -> 8 per thread
    const int cprowB = tid >> 4;
    const int cpsegB = tid & 15;

    // MMA warp tiling
    const int warp_m = wid >> 2;
    const int warp_n = wid & 3;
    const int lrow = lane & 15;
    const int lgrp = lane >> 4;
    const uint32_t a_lane_off = ((warp_m * 16 + lrow) * SA_STRIDE + lgrp * 8) * 2;
    const uint32_t b_lane_off = (lrow * SB_STRIDE + warp_n * 32 + lgrp * 8) * 2;

    float acc[4][4];
#pragma unroll
    for (int nf = 0; nf < 4; nf++)
#pragma unroll
        for (int q = 0; q < 4; q++) acc[nf][q] = 0.f;

    // ---- prologue: prefetch B(0) into stage 0; stage-A(0) into A buf 0 ----
#pragma unroll
    for (int p = 0; p < 8; p++) {
        const int r = cprowB + p * 16;
        cp16(sb + r * 272 + cpsegB * 16,
             (const char*)g_h16 + ((size_t)r * WFEAT + cpsegB * 8) * 2);
    }
    cp_commit();
    {
        const uint4 mw0 = __ldg(&mrow4[0]);
        float4 d40[4];
#pragma unroll
        for (int g = 0; g < 4; g++)
            d40[g] = __ldg((const float4*)&g_fdst[baseCol + g * 4]);
        stage_a(smem, OFF_A, 0, fs, Cr, att_row, mw0, d40, arow, baseCol);
    }

#pragma unroll 2
    for (int it = 0; it < NIT; it++) {
        const int b = it & 1;

        cp_wait0();        // own share of B(it) landed
        __syncthreads();   // all shares + A[b] visible; MMA(it-1) done -> buffers free

        // --- register-prefetch stage-A(it+1) operands (latency hidden by MMA) ---
        uint4 mw_n = make_uint4(0u, 0u, 0u, 0u);
        float4 d4_n[4];
#pragma unroll
        for (int g = 0; g < 4; g++) d4_n[g] = make_float4(0.f, 0.f, 0.f, 0.f);
        if (it + 1 < NIT) {
            mw_n = __ldg(&mrow4[it + 1]);
#pragma unroll
            for (int g = 0; g < 4; g++)
                d4_n[g] = __ldg((const float4*)&g_fdst[(it + 1) * 128 + baseCol + g * 4]);
        }

        // --- prefetch B(it+1) into stage 1-b (last read by MMA(it-1)) ---
        if (it + 1 < NIT) {
            const int jb = (it + 1) * 128;
            const uint32_t bs = sb + (1 - b) * B_BUF;
#pragma unroll
            for (int p = 0; p < 8; p++) {
                const int r = cprowB + p * 16;
                cp16(bs + r * 272 + cpsegB * 16,
                     (const char*)g_h16 + ((size_t)(jb + r) * WFEAT + cpsegB * 8) * 2);
            }
        }
        cp_commit();

        // --- MMA(it): 8 k16 steps, A from buf b, B from stage b ---
        const uint32_t a_base = sb + OFF_A + b * A_BUF + a_lane_off;
        const uint32_t bh_base = sb + b * B_BUF + b_lane_off;
#pragma unroll
        for (int ks = 0; ks < 8; ks++) {
            uint32_t ah[4], bh[2][4];
            ldsm_x4(ah, a_base + (ks * 16) * 2);
#pragma unroll
            for (int pr = 0; pr < 2; pr++) {
                const uint32_t boff = (ks * 16 * SB_STRIDE + pr * 16) * 2;
                ldsm_x4_t(bh[pr], bh_base + boff);
            }
#pragma unroll
            for (int nf = 0; nf < 4; nf++)
                mma_f16(acc[nf], ah, &bh[nf >> 1][(nf & 1) * 2]);
        }

        // --- stage-A(it+1) into A buf 1-b (last read by MMA(it-1)) ---
        if (it + 1 < NIT)
            stage_a(smem, OFF_A + (1 - b) * A_BUF, it + 1, fs, Cr,
                    att_row, mw_n, d4_n, arow, baseCol);
    }

    // --- epilogue: sentence tile + fused column-max pooling ---
    const int grp = lane >> 2;
    const int tig = lane & 3;
    float cmax[4][2];
#pragma unroll
    for (int nf = 0; nf < 4; nf++) {
        const int row0 = i0 + warp_m * 16 + grp;
        const int col  = warp_n * 32 + nf * 8 + tig * 2;
        __stcs((float2*)&sen_out[(size_t)row0 * WFEAT + col],
               make_float2(acc[nf][0], acc[nf][1]));
        __stcs((float2*)&sen_out[(size_t)(row0 + 8) * WFEAT + col],
               make_float2(acc[nf][2], acc[nf][3]));
        cmax[nf][0] = fmaxf(acc[nf][0], acc[nf][2]);
        cmax[nf][1] = fmaxf(acc[nf][1], acc[nf][3]);
    }
#pragma unroll
    for (int off = 4; off <= 16; off <<= 1)
#pragma unroll
        for (int nf = 0; nf < 4; nf++) {
            cmax[nf][0] = fmaxf(cmax[nf][0], __shfl_xor_sync(0xffffffffu, cmax[nf][0], off));
            cmax[nf][1] = fmaxf(cmax[nf][1], __shfl_xor_sync(0xffffffffu, cmax[nf][1], off));
        }
    __syncthreads();
    float* pm = (float*)smem;              // pm[2][128]
    if (grp == 0) {
#pragma unroll
        for (int nf = 0; nf < 4; nf++) {
            pm[warp_m * 128 + warp_n * 32 + nf * 8 + tig * 2]     = cmax[nf][0];
            pm[warp_m * 128 + warp_n * 32 + nf * 8 + tig * 2 + 1] = cmax[nf][1];
        }
    }
    __syncthreads();
    if (tid < 128)
        g_pmax[blockIdx.x * WFEAT + tid] = fmaxf(pm[tid], pm[128 + tid]);
}

// ---------------- K5: final pool + classifier ----------------
__global__ __launch_bounds__(1024) void k5_head(const float* __restrict__ cls_W,
                                                const float* __restrict__ cls_b,
                                                float* __restrict__ pool_out,
                                                float* __restrict__ lab_out) {
    const int tid  = threadIdx.x;
    const int col  = tid & 127;
    const int part = tid >> 7;
    __shared__ float pp[8][WFEAT];
    __shared__ float pool[WFEAT];

    float m = NEGINF;
    const int b0 = part * 32;
#pragma unroll 8
    for (int b = 0; b < 32; b++)
        m = fmaxf(m, __ldg(&g_pmax[(b0 + b) * WFEAT + col]));
    pp[part][col] = m;
    __syncthreads();

    if (tid < 128) {
        float mm = pp[0][tid];
#pragma unroll
        for (int p = 1; p < 8; p++) mm = fmaxf(mm, pp[p][tid]);
        pool[tid] = mm;
        pool_out[tid] = mm;
    }
    __syncthreads();

    if (tid < 32) {
        float l0 = 0.f, l1 = 0.f;
#pragma unroll
        for (int q = 0; q < 4; q++) {
            const int k = tid * 4 + q;
            const float pv = pool[k];
            l0 += pv * __ldg(&cls_W[2 * k]);
            l1 += pv * __ldg(&cls_W[2 * k + 1]);
        }
#pragma unroll
        for (int off = 16; off > 0; off >>= 1) {
            l0 += __shfl_xor_sync(0xffffffffu, l0, off);
            l1 += __shfl_xor_sync(0xffffffffu, l1, off);
        }
        if (tid == 0) {
            l0 += __ldg(&cls_b[0]);
            l1 += __ldg(&cls_b[1]);
            const float mm = fmaxf(l0, l1);
            const float e0 = __expf(l0 - mm), e1 = __expf(l1 - mm);
            const float inv = 1.0f / (e0 + e1);
            lab_out[0] = e0 * inv;
            lab_out[1] = e1 * inv;
        }
    }
}

// ---------------- launch ----------------
extern "C" void kernel_launch(void* const* d_in, const int* in_sizes, int n_in,
                              void* d_out, int out_size) {
    const int*   inSen    = (const int*)d_in[0];
    const int*   adj      = (const int*)d_in[1];
    const int*   selfLink = (const int*)d_in[2];
    const float* emb      = (const float*)d_in[3];
    const float* W        = (const float*)d_in[4];
    const float* a_src    = (const float*)d_in[5];
    const float* a_dst    = (const float*)d_in[6];
    const float* cls_W    = (const float*)d_in[7];
    const float* cls_b    = (const float*)d_in[8];

    float* out      = (float*)d_out;
    float* pool_out = out;
    float* att_out  = out + WFEAT;
    float* sen_out  = att_out + (size_t)N * N;
    float* lab_out  = sen_out + (size_t)N * WFEAT;

    static int configured = 0;
    if (!configured) {
        cudaFuncSetAttribute(k3_hmma, cudaFuncAttributeMaxDynamicSharedMemorySize, K3_SMEM);
        configured = 1;
    }

    k1_proj<<<N / 16, 128>>>(inSen, emb, W, a_src, a_dst);
    k2_stats<<<N, 256>>>(adj, selfLink);
    k3_hmma<<<N / 32, 256, K3_SMEM>>>(att_out, sen_out);
    k5_head<<<1, 1024>>>(cls_W, cls_b, pool_out, lab_out);
}